// round 7
// baseline (speedup 1.0000x reference)
#include <cuda_runtime.h>
#include <cuda_bf16.h>
#include <math.h>

// Problem dims (fixed)
#define T_DIM 8192
#define M_DIM 1024
#define N_DIM 2048

#define GR   128     // recurrence CTAs (all resident on 148 SMs)
#define RPB  16      // rows of W_hh per CTA (2 per warp)
#define RTHR 256
#define NCH  32      // column chunks of 64 (2 per lane) : 32*64 = 2048

// ---------------- scratch + sync state (no allocations allowed) -------------
__device__ float g_pre[(size_t)T_DIM * N_DIM];   // 64 MB: pre = X@W_ih^T + b
__device__ float g_h0[N_DIM];                    // static zeros -> h_{-1}
__device__ unsigned g_cnt[T_DIM];                // per-step arrival counters

__global__ void init_cnt_kernel() {
    for (int i = threadIdx.x; i < T_DIM; i += blockDim.x) g_cnt[i] = 0u;
}

// ---------------- Kernel A: pre = X @ W_ih^T + (b_ih + b_hh) ----------------
// 128x128 tile, BK=8, 256 threads, 8x8 microtile, f32x2-packed inner loop.
__global__ __launch_bounds__(256) void gemm_pre_kernel(
    const float* __restrict__ X,
    const float* __restrict__ Wih,
    const float* __restrict__ b_ih,
    const float* __restrict__ b_hh)
{
    __shared__ float As[8][128];
    __shared__ float Bs[8][128];

    const int tx   = threadIdx.x;
    const int row0 = blockIdx.y * 128;
    const int col0 = blockIdx.x * 128;

    const int lr = tx >> 1;
    const int lc = (tx & 1) << 2;
    const int trow = (tx >> 4) << 3;
    const int tcol = (tx & 15) << 3;

    unsigned long long acc2[8][4];
#pragma unroll
    for (int i = 0; i < 8; i++)
#pragma unroll
        for (int j = 0; j < 4; j++) acc2[i][j] = 0ull;

    const float* Xp = X   + (size_t)(row0 + lr) * M_DIM + lc;
    const float* Wp = Wih + (size_t)(col0 + lr) * M_DIM + lc;

    for (int k0 = 0; k0 < M_DIM; k0 += 8) {
        float4 a = *(const float4*)(Xp + k0);
        float4 b = *(const float4*)(Wp + k0);
        As[lc + 0][lr] = a.x; As[lc + 1][lr] = a.y;
        As[lc + 2][lr] = a.z; As[lc + 3][lr] = a.w;
        Bs[lc + 0][lr] = b.x; Bs[lc + 1][lr] = b.y;
        Bs[lc + 2][lr] = b.z; Bs[lc + 3][lr] = b.w;
        __syncthreads();

#pragma unroll
        for (int k = 0; k < 8; k++) {
            float ar[8];
#pragma unroll
            for (int i = 0; i < 8; i++) ar[i] = As[k][trow + i];
            const unsigned long long* bp =
                (const unsigned long long*)&Bs[k][tcol];
            unsigned long long br2[4] = { bp[0], bp[1], bp[2], bp[3] };
#pragma unroll
            for (int i = 0; i < 8; i++) {
                unsigned long long ap;
                asm("mov.b64 %0, {%1, %1};" : "=l"(ap) : "f"(ar[i]));
#pragma unroll
                for (int j = 0; j < 4; j++)
                    asm("fma.rn.f32x2 %0, %1, %2, %3;"
                        : "=l"(acc2[i][j]) : "l"(ap), "l"(br2[j]), "l"(acc2[i][j]));
            }
        }
        __syncthreads();
    }

    float bias[8];
#pragma unroll
    for (int j = 0; j < 8; j++)
        bias[j] = b_ih[col0 + tcol + j] + b_hh[col0 + tcol + j];

#pragma unroll
    for (int i = 0; i < 8; i++) {
        float out8[8];
#pragma unroll
        for (int j = 0; j < 4; j++) {
            float lo, hi;
            asm("mov.b64 {%0, %1}, %2;" : "=f"(lo), "=f"(hi) : "l"(acc2[i][j]));
            out8[2 * j]     = lo + bias[2 * j];
            out8[2 * j + 1] = hi + bias[2 * j + 1];
        }
        float4* out = (float4*)&g_pre[(size_t)(row0 + trow + i) * N_DIM + col0 + tcol];
        out[0] = make_float4(out8[0], out8[1], out8[2], out8[3]);
        out[1] = make_float4(out8[4], out8[5], out8[6], out8[7]);
    }
}

// ---------------- fast tanh (MUFU.EX2 based, ~1e-7 rel err) -----------------
__device__ __forceinline__ float fast_tanh(float x) {
    float e = __expf(-2.0f * x);
    return __fdividef(2.0f, 1.0f + e) - 1.0f;
}

// ---------------- Kernel B: persistent recurrence ---------------------------
// Warp w owns rows base+2w, base+2w+1 ENTIRELY. Lane l owns column pairs
// (64c + 2l, 64c + 2l + 1) for c = 0..31 -> coalesced 8B h loads, weights
// pre-packed as f32x2. No smem, no partial phase: per-lane f32x2 accumulate
// (2 chains per row), one shfl_xor tree per row.
__global__ __launch_bounds__(RTHR, 1) void recur_kernel(
    const float* __restrict__ Whh,
    float* __restrict__ Y)
{
    const int tid  = threadIdx.x;
    const int base = blockIdx.x * RPB;
    const int warp = tid >> 5;
    const int lane = tid & 31;
    const int r0   = base + 2 * warp;    // this warp's first row

    // Weights: lane l holds rows r0, r0+1 at cols {64c+2l, 64c+2l+1}.
    unsigned long long w0[NCH], w1[NCH];
    {
        const unsigned long long* p0 =
            (const unsigned long long*)&Whh[(size_t)r0 * N_DIM];
        const unsigned long long* p1 =
            (const unsigned long long*)&Whh[(size_t)(r0 + 1) * N_DIM];
#pragma unroll
        for (int c = 0; c < NCH; c++) {
            w0[c] = p0[32 * c + lane];
            w1[c] = p1[32 * c + lane];
        }
    }

    for (int t = 0; t < T_DIM; t++) {
        // Prefetch pre for this warp's two rows (h-independent; warp bcast).
        const float2 pre2 = *(const float2*)&g_pre[(size_t)t * N_DIM + r0];

        // Single-poller barrier: all 128 CTAs finished step t-1.
        if (t > 0) {
            if (tid == 0) {
                const unsigned* cp = &g_cnt[t - 1];
                unsigned c;
                do {
                    asm volatile("ld.acquire.gpu.global.u32 %0, [%1];"
                                 : "=r"(c) : "l"(cp) : "memory");
                } while (c < (unsigned)GR);
            }
            __syncthreads();   // fan the acquire to all threads
        }

        const float* hp = (t == 0) ? g_h0 : (Y + (size_t)(t - 1) * N_DIM);
        const unsigned long long* hq = (const unsigned long long*)hp;

        // 4 independent FMA chains (2 per row) over 32 chunks.
        unsigned long long a0a = 0ull, a0b = 0ull, a1a = 0ull, a1b = 0ull;
#pragma unroll
        for (int c = 0; c < NCH; c += 2) {
            unsigned long long hva = hq[32 * c + lane];
            unsigned long long hvb = hq[32 * (c + 1) + lane];
            asm("fma.rn.f32x2 %0, %1, %2, %3;"
                : "=l"(a0a) : "l"(w0[c]),     "l"(hva), "l"(a0a));
            asm("fma.rn.f32x2 %0, %1, %2, %3;"
                : "=l"(a1a) : "l"(w1[c]),     "l"(hva), "l"(a1a));
            asm("fma.rn.f32x2 %0, %1, %2, %3;"
                : "=l"(a0b) : "l"(w0[c + 1]), "l"(hvb), "l"(a0b));
            asm("fma.rn.f32x2 %0, %1, %2, %3;"
                : "=l"(a1b) : "l"(w1[c + 1]), "l"(hvb), "l"(a1b));
        }
        asm("add.rn.f32x2 %0, %1, %2;" : "=l"(a0a) : "l"(a0a), "l"(a0b));
        asm("add.rn.f32x2 %0, %1, %2;" : "=l"(a1a) : "l"(a1a), "l"(a1b));

        float s0, s1;
        {
            float lo, hi;
            asm("mov.b64 {%0, %1}, %2;" : "=f"(lo), "=f"(hi) : "l"(a0a));
            s0 = lo + hi;
            asm("mov.b64 {%0, %1}, %2;" : "=f"(lo), "=f"(hi) : "l"(a1a));
            s1 = lo + hi;
        }
#pragma unroll
        for (int o = 16; o > 0; o >>= 1) {
            s0 += __shfl_xor_sync(0xffffffffu, s0, o);
            s1 += __shfl_xor_sync(0xffffffffu, s1, o);
        }

        if (lane == 0) {
            float2 v;
            v.x = fast_tanh(s0 + pre2.x);
            v.y = fast_tanh(s1 + pre2.y);
            *(float2*)&Y[(size_t)t * N_DIM + r0] = v;
        }

        __syncthreads();     // join: all warps' Y stores for step t issued

        if (tid == 0) {
            asm volatile("red.release.gpu.global.add.u32 [%0], %1;"
                         :: "l"(&g_cnt[t]), "r"(1u) : "memory");
        }
    }
}

// ---------------- launch ----------------------------------------------------
extern "C" void kernel_launch(void* const* d_in, const int* in_sizes, int n_in,
                              void* d_out, int out_size)
{
    const float* X    = (const float*)d_in[0];  // (T, M)
    const float* Wih  = (const float*)d_in[1];  // (N, M)
    const float* Whh  = (const float*)d_in[2];  // (N, N)
    const float* b_ih = (const float*)d_in[3];  // (N,)
    const float* b_hh = (const float*)d_in[4];  // (N,)
    float* Y = (float*)d_out;                   // (T, N)

    init_cnt_kernel<<<1, 256>>>();

    dim3 ggrid(N_DIM / 128, T_DIM / 128);       // (16, 64)
    gemm_pre_kernel<<<ggrid, 256>>>(X, Wih, b_ih, b_hh);

    recur_kernel<<<GR, RTHR>>>(Whh, Y);
}

// round 10
// speedup vs baseline: 1.0166x; 1.0166x over previous
#include <cuda_runtime.h>
#include <cuda_bf16.h>
#include <math.h>

// Problem dims (fixed)
#define T_DIM 8192
#define M_DIM 1024
#define N_DIM 2048

#define GR   128     // recurrence CTAs (all resident on 148 SMs)
#define RPB  16      // rows of W_hh per CTA
#define RTHR 256

// ---------------- scratch + sync state (no allocations allowed) -------------
__device__ float g_pre[(size_t)T_DIM * N_DIM];   // 64 MB: pre = X@W_ih^T + b
__device__ float g_h0[N_DIM];                    // static zeros -> h_{-1}
__device__ unsigned g_cnt[T_DIM];                // per-step arrival counters

__global__ void init_cnt_kernel() {
    for (int i = threadIdx.x; i < T_DIM; i += blockDim.x) g_cnt[i] = 0u;
}

// ---------------- Kernel A: pre = X @ W_ih^T + (b_ih + b_hh) ----------------
// 128x128 tile, BK=8, 256 threads, 8x8 microtile, f32x2-packed inner loop.
__global__ __launch_bounds__(256) void gemm_pre_kernel(
    const float* __restrict__ X,
    const float* __restrict__ Wih,
    const float* __restrict__ b_ih,
    const float* __restrict__ b_hh)
{
    __shared__ float As[8][128];
    __shared__ float Bs[8][128];

    const int tx   = threadIdx.x;
    const int row0 = blockIdx.y * 128;
    const int col0 = blockIdx.x * 128;

    const int lr = tx >> 1;
    const int lc = (tx & 1) << 2;
    const int trow = (tx >> 4) << 3;
    const int tcol = (tx & 15) << 3;

    unsigned long long acc2[8][4];
#pragma unroll
    for (int i = 0; i < 8; i++)
#pragma unroll
        for (int j = 0; j < 4; j++) acc2[i][j] = 0ull;

    const float* Xp = X   + (size_t)(row0 + lr) * M_DIM + lc;
    const float* Wp = Wih + (size_t)(col0 + lr) * M_DIM + lc;

    for (int k0 = 0; k0 < M_DIM; k0 += 8) {
        float4 a = *(const float4*)(Xp + k0);
        float4 b = *(const float4*)(Wp + k0);
        As[lc + 0][lr] = a.x; As[lc + 1][lr] = a.y;
        As[lc + 2][lr] = a.z; As[lc + 3][lr] = a.w;
        Bs[lc + 0][lr] = b.x; Bs[lc + 1][lr] = b.y;
        Bs[lc + 2][lr] = b.z; Bs[lc + 3][lr] = b.w;
        __syncthreads();

#pragma unroll
        for (int k = 0; k < 8; k++) {
            float ar[8];
#pragma unroll
            for (int i = 0; i < 8; i++) ar[i] = As[k][trow + i];
            const unsigned long long* bp =
                (const unsigned long long*)&Bs[k][tcol];
            unsigned long long br2[4] = { bp[0], bp[1], bp[2], bp[3] };
#pragma unroll
            for (int i = 0; i < 8; i++) {
                unsigned long long ap;
                asm("mov.b64 %0, {%1, %1};" : "=l"(ap) : "f"(ar[i]));
#pragma unroll
                for (int j = 0; j < 4; j++)
                    asm("fma.rn.f32x2 %0, %1, %2, %3;"
                        : "=l"(acc2[i][j]) : "l"(ap), "l"(br2[j]), "l"(acc2[i][j]));
            }
        }
        __syncthreads();
    }

    float bias[8];
#pragma unroll
    for (int j = 0; j < 8; j++)
        bias[j] = b_ih[col0 + tcol + j] + b_hh[col0 + tcol + j];

#pragma unroll
    for (int i = 0; i < 8; i++) {
        float out8[8];
#pragma unroll
        for (int j = 0; j < 4; j++) {
            float lo, hi;
            asm("mov.b64 {%0, %1}, %2;" : "=f"(lo), "=f"(hi) : "l"(acc2[i][j]));
            out8[2 * j]     = lo + bias[2 * j];
            out8[2 * j + 1] = hi + bias[2 * j + 1];
        }
        float4* out = (float4*)&g_pre[(size_t)(row0 + trow + i) * N_DIM + col0 + tcol];
        out[0] = make_float4(out8[0], out8[1], out8[2], out8[3]);
        out[1] = make_float4(out8[4], out8[5], out8[6], out8[7]);
    }
}

// ---------------- fast tanh (MUFU.EX2 based, ~1e-7 rel err) -----------------
__device__ __forceinline__ float fast_tanh(float x) {
    float e = __expf(-2.0f * x);
    return __fdividef(2.0f, 1.0f + e) - 1.0f;
}

// ---------------- Kernel B: persistent recurrence ---------------------------
// 2-D warp tiling: warp (rg,cg) with rg=warp>>2, cg=warp&3 owns rows
// base+8*rg..+8 over cols [512*cg, 512*cg+512). Lane l owns 16 consecutive
// cols -> 4 LDG.128 of h per thread (coalesced), h read only 2x per CTA.
// Reduce: in-register transpose shfl-reduce (8 vals over 32 lanes, 16 shfls,
// bit-reversed row permutation), 64-float smem exchange, warp0 finishes
// 16 outputs + releases. Two bars per step.
__global__ __launch_bounds__(RTHR, 1) void recur_kernel(
    const float* __restrict__ Whh,
    float* __restrict__ Y)
{
    const int tid  = threadIdx.x;
    const int base = blockIdx.x * RPB;
    const int warp = tid >> 5;
    const int lane = tid & 31;
    const int rg   = warp >> 2;          // 0..1 : row group (8 rows)
    const int cg   = warp & 3;           // 0..3 : col group (512 cols)
    const int col0 = cg * 512 + lane * 16;
    const int row0 = base + rg * 8;

    // Weights: w2[r][k] = W_hh[row0+r][col0 + 2k .. 2k+1], k=0..7 (16 cols).
    unsigned long long w2[8][8];
#pragma unroll
    for (int r = 0; r < 8; r++) {
        const ulonglong2* p =
            (const ulonglong2*)&Whh[(size_t)(row0 + r) * N_DIM + col0];
#pragma unroll
        for (int q = 0; q < 4; q++) {
            ulonglong2 v = p[q];
            w2[r][2 * q]     = v.x;
            w2[r][2 * q + 1] = v.y;
        }
    }

    __shared__ float sred[RPB][4];       // [row within CTA][col group]

    for (int t = 0; t < T_DIM; t++) {
        // Prefetch pre for warp0's 16 outputs (h-independent).
        float pre_l = 0.0f;
        if (warp == 0 && lane < 16)
            pre_l = g_pre[(size_t)t * N_DIM + base + lane];

        // Single-poller barrier: all 128 CTAs finished step t-1.
        if (t > 0) {
            if (tid == 0) {
                const unsigned* cp = &g_cnt[t - 1];
                unsigned c;
                do {
                    asm volatile("ld.acquire.gpu.global.u32 %0, [%1];"
                                 : "=r"(c) : "l"(cp) : "memory");
                } while (c < (unsigned)GR);
            }
            __syncthreads();   // fan: extends tid0's acquire to all threads
        }

        const float* hp = (t == 0) ? g_h0 : (Y + (size_t)(t - 1) * N_DIM);

        // Load this lane's 16 h values (4x LDG.128, coalesced across warp).
        unsigned long long h2[8];
        {
            const ulonglong2* hq = (const ulonglong2*)(hp + col0);
#pragma unroll
            for (int q = 0; q < 4; q++) {
                ulonglong2 v = hq[q];
                h2[2 * q]     = v.x;
                h2[2 * q + 1] = v.y;
            }
        }

        // 8 independent FMA chains (one per row).
        float s[8];
#pragma unroll
        for (int r = 0; r < 8; r++) {
            unsigned long long acc;
            asm("mul.rn.f32x2 %0, %1, %2;"
                : "=l"(acc) : "l"(w2[r][0]), "l"(h2[0]));
#pragma unroll
            for (int k = 1; k < 8; k++)
                asm("fma.rn.f32x2 %0, %1, %2, %3;"
                    : "=l"(acc) : "l"(w2[r][k]), "l"(h2[k]), "l"(acc));
            float lo, hi;
            asm("mov.b64 {%0, %1}, %2;" : "=f"(lo), "=f"(hi) : "l"(acc));
            s[r] = lo + hi;
        }

        // Transpose shfl-reduce: 8 values over 32 lanes -> lane<8 holds one
        // fully-reduced row. Row at lane l: 4*(l&1) + (l&2) + ((l>>2)&1).
        {
            // Round o=1: even lanes keep rows 0..3, odd keep rows 4..7.
#pragma unroll
            for (int j = 0; j < 4; j++) {
                float rl = __shfl_xor_sync(0xffffffffu, s[j], 1);
                float rh = __shfl_xor_sync(0xffffffffu, s[j + 4], 1);
                s[j] = (lane & 1) ? (s[j + 4] + rh) : (s[j] + rl);
            }
            // Round o=2.
#pragma unroll
            for (int j = 0; j < 2; j++) {
                float rl = __shfl_xor_sync(0xffffffffu, s[j], 2);
                float rh = __shfl_xor_sync(0xffffffffu, s[j + 2], 2);
                s[j] = (lane & 2) ? (s[j + 2] + rh) : (s[j] + rl);
            }
            // Round o=4.
            {
                float rl = __shfl_xor_sync(0xffffffffu, s[0], 4);
                float rh = __shfl_xor_sync(0xffffffffu, s[1], 4);
                s[0] = (lane & 4) ? (s[1] + rh) : (s[0] + rl);
            }
            // Rounds o=8,16: same-row duplicates.
            s[0] += __shfl_xor_sync(0xffffffffu, s[0], 8);
            s[0] += __shfl_xor_sync(0xffffffffu, s[0], 16);
        }

        if (lane < 8) {
            const int rloc = (lane & 1) * 4 + (lane & 2) + ((lane >> 2) & 1);
            sred[rg * 8 + rloc][cg] = s[0];
        }
        __syncthreads();   // mid: sred complete

        // Warp 0 lanes 0..15 finish the 16 outputs and release.
        if (warp == 0) {
            if (lane < 16) {
                float4 p4 = *(const float4*)&sred[lane][0];
                float v = fast_tanh((p4.x + p4.y) + (p4.z + p4.w) + pre_l);
                Y[(size_t)t * N_DIM + base + lane] = v;
            }
            __syncwarp();
            if (lane == 0) {
                asm volatile("red.release.gpu.global.add.u32 [%0], %1;"
                             :: "l"(&g_cnt[t]), "r"(1u) : "memory");
            }
        }
        // Other warps run ahead to the next fan bar; sred is not rewritten
        // until after that bar, which warp0 reaches only after its LDS here.
    }
}

// ---------------- launch ----------------------------------------------------
extern "C" void kernel_launch(void* const* d_in, const int* in_sizes, int n_in,
                              void* d_out, int out_size)
{
    const float* X    = (const float*)d_in[0];  // (T, M)
    const float* Wih  = (const float*)d_in[1];  // (N, M)
    const float* Whh  = (const float*)d_in[2];  // (N, N)
    const float* b_ih = (const float*)d_in[3];  // (N,)
    const float* b_hh = (const float*)d_in[4];  // (N,)
    float* Y = (float*)d_out;                   // (T, N)

    init_cnt_kernel<<<1, 256>>>();

    dim3 ggrid(N_DIM / 128, T_DIM / 128);       // (16, 64)
    gemm_pre_kernel<<<ggrid, 256>>>(X, Wih, b_ih, b_hh);

    recur_kernel<<<GR, RTHR>>>(Whh, Y);
}